// round 2
// baseline (speedup 1.0000x reference)
#include <cuda_runtime.h>
#include <math.h>

// Problem shape (fixed by the dataset)
#define BMAX   4
#define NN     4096
#define DDIM   1024
#define MSPLIT 32
#define MCHUNK (NN / MSPLIT)   // 128
#define DTILE  256
#define EPSV   1e-6f
#define ROWS_PER_BLOCK 8

// Scratch (device globals: no allocation allowed)
__device__ float g_part[BMAX][MSPLIT][3][DDIM]; // partial H0/Hc/Hs
__device__ float g_H[BMAX][3][DDIM];            // reduced H0/Hc/Hs
__device__ float g_CS[BMAX][2];                 // sum cos, sum sin

// ---------------------------------------------------------------------------
// Kernel 0: per-batch sum of cos(phase), sin(phase). One block per batch.
// ---------------------------------------------------------------------------
__global__ void kernel_cs(const float* __restrict__ phases) {
    __shared__ float sc[1024], ss[1024];
    int b = blockIdx.x;
    int t = threadIdx.x;
    float ac = 0.f, as = 0.f;
    for (int m = t; m < NN; m += 1024) {
        float p = phases[b * NN + m];
        float c, s;
        __sincosf(p, &s, &c);       // fast path; refine below
        // use precise sincos for accuracy (weights feed a 4096-sum)
        s = sinf(p); c = cosf(p);
        ac += c; as += s;
    }
    sc[t] = ac; ss[t] = as;
    __syncthreads();
    for (int off = 512; off > 0; off >>= 1) {
        if (t < off) { sc[t] += sc[t + off]; ss[t] += ss[t + off]; }
        __syncthreads();
    }
    if (t == 0) { g_CS[b][0] = sc[0]; g_CS[b][1] = ss[0]; }
}

// ---------------------------------------------------------------------------
// Kernel 1: partial reductions of H0/Hc/Hs over m-chunks.
// grid = (DDIM/DTILE, MSPLIT, B), block = 256 threads (one d each).
// ---------------------------------------------------------------------------
__global__ void kernel_part(const float* __restrict__ hidden,
                            const float* __restrict__ phases) {
    __shared__ float smc[MCHUNK], sms[MCHUNK];
    const int b  = blockIdx.z;
    const int ms = blockIdx.y;
    const int d  = blockIdx.x * DTILE + threadIdx.x;
    const int m0 = ms * MCHUNK;

    if (threadIdx.x < MCHUNK) {
        float p = phases[b * NN + m0 + threadIdx.x];
        smc[threadIdx.x] = cosf(p);
        sms[threadIdx.x] = sinf(p);
    }
    __syncthreads();

    const float* hp = hidden + ((size_t)b * NN + m0) * DDIM + d;
    float a0 = 0.f, ac = 0.f, as = 0.f;
#pragma unroll 4
    for (int m = 0; m < MCHUNK; ++m) {
        float h = hp[(size_t)m * DDIM];
        a0 += h;
        ac += smc[m] * h;
        as += sms[m] * h;
    }
    g_part[b][ms][0][d] = a0;
    g_part[b][ms][1][d] = ac;
    g_part[b][ms][2][d] = as;
}

// ---------------------------------------------------------------------------
// Kernel 2: fold MSPLIT partials -> g_H. grid = (DDIM/256, B), block = 256.
// ---------------------------------------------------------------------------
__global__ void kernel_reduce() {
    int b = blockIdx.y;
    int d = blockIdx.x * 256 + threadIdx.x;
    float a0 = 0.f, ac = 0.f, as = 0.f;
#pragma unroll 8
    for (int ms = 0; ms < MSPLIT; ++ms) {
        a0 += g_part[b][ms][0][d];
        ac += g_part[b][ms][1][d];
        as += g_part[b][ms][2][d];
    }
    g_H[b][0][d] = a0;
    g_H[b][1][d] = ac;
    g_H[b][2][d] = as;
}

// ---------------------------------------------------------------------------
// Kernel 3: output pass. grid = (NN/ROWS_PER_BLOCK, B), block = 256.
// Each thread handles 4 consecutive d (float4). H vectors staged in smem.
// ---------------------------------------------------------------------------
__global__ void kernel_out(const float* __restrict__ hidden,
                           const float* __restrict__ phases,
                           const float* __restrict__ alpha_p,
                           float* __restrict__ out) {
    __shared__ float sH0[DDIM], sHc[DDIM], sHs[DDIM];
    const int b  = blockIdx.y;
    const int n0 = blockIdx.x * ROWS_PER_BLOCK;
    const int t  = threadIdx.x;

    // stage H vectors (1024 floats each, 256 threads -> 4 each)
#pragma unroll
    for (int i = 0; i < 4; ++i) {
        int d = t + i * 256;
        sH0[d] = g_H[b][0][d];
        sHc[d] = g_H[b][1][d];
        sHs[d] = g_H[b][2][d];
    }
    __syncthreads();

    float alpha = alpha_p[0];
    alpha = fminf(fmaxf(alpha, 0.f), 1.f);
    const float one_m_a = 1.f - alpha;
    const float C = g_CS[b][0];
    const float S = g_CS[b][1];

    const int d4 = t * 4;
    const float4* h0v = (const float4*)(sH0 + d4);
    const float4* hcv = (const float4*)(sHc + d4);
    const float4* hsv = (const float4*)(sHs + d4);
    float4 H0 = *h0v, Hc = *hcv, Hs = *hsv;

    for (int r = 0; r < ROWS_PER_BLOCK; ++r) {
        int n = n0 + r;
        float p = phases[b * NN + n];
        float cn = cosf(p), sn = sinf(p);
        float den = fmaxf(0.5f * ((float)NN + cn * C + sn * S), EPSV);
        float tcoef = alpha * 0.5f / den;   // a * 0.5 / den

        const float4* hv = (const float4*)(hidden + ((size_t)b * NN + n) * DDIM + d4);
        float4* ov       = (float4*)(out   + ((size_t)b * NN + n) * DDIM + d4);
        float4 h = *hv;
        float4 o;
        o.x = tcoef * (H0.x + cn * Hc.x + sn * Hs.x) + one_m_a * h.x;
        o.y = tcoef * (H0.y + cn * Hc.y + sn * Hs.y) + one_m_a * h.y;
        o.z = tcoef * (H0.z + cn * Hc.z + sn * Hs.z) + one_m_a * h.z;
        o.w = tcoef * (H0.w + cn * Hc.w + sn * Hs.w) + one_m_a * h.w;
        *ov = o;
    }
}

// ---------------------------------------------------------------------------
// Launch
// ---------------------------------------------------------------------------
extern "C" void kernel_launch(void* const* d_in, const int* in_sizes, int n_in,
                              void* d_out, int out_size) {
    const float* hidden = (const float*)d_in[0];
    const float* phases = (const float*)d_in[1];
    const float* alpha  = (const float*)d_in[2];
    float* out = (float*)d_out;

    const int B = in_sizes[1] / NN;   // 16384 / 4096 = 4

    kernel_cs<<<B, 1024>>>(phases);
    kernel_part<<<dim3(DDIM / DTILE, MSPLIT, B), DTILE>>>(hidden, phases);
    kernel_reduce<<<dim3(DDIM / 256, B), 256>>>();
    kernel_out<<<dim3(NN / ROWS_PER_BLOCK, B), 256>>>(hidden, phases, alpha, out);
}